// round 3
// baseline (speedup 1.0000x reference)
#include <cuda_runtime.h>
#include <cuda_bf16.h>

// Problem constants (fixed by the reference: B=16,S=16 -> BS=256)
#define L_TOK   128          // tokens per sentence
#define NARG    8            // A
#define NTOK    8            // T
#define EMB_D   768          // D
#define DC      256          // D-chunk per CTA
#define NCHUNK  (EMB_D / DC) // 3
#define NP      24           // 3 arg-sets * NARG
#define BDIM    256

// Shared memory: per-thread arg accumulators + per-token event lists.
struct SmemLayout {
    float acc[NP * BDIM];            // 24 KB  acc[p*BDIM + tid], conflict-free
    int   s_ids[L_TOK];              // sentence ids
    float s_m[L_TOK];                // attention mask (as float)
    int   s_arg[NP * NTOK];          // arg ids, [p][t]
    unsigned short ev[L_TOK * NP];   // 6 KB  per-token events: p | (w<<5)
    int   ev_cnt[L_TOK];             // events per token
    int   s_tot[NP];                 // total matched-token count per p
    float s_inv[NP];                 // 1/tot, or 0 if tot==0
    float s_minv;                    // 1/max(sum(mask),1)
};

__global__ void __launch_bounds__(BDIM)
slmuse_fused_kernel(const int*   __restrict__ sent_ids,
                    const int*   __restrict__ att_mask,
                    const int*   __restrict__ pred_ids,
                    const int*   __restrict__ arg0_ids,
                    const int*   __restrict__ arg1_ids,
                    const float* __restrict__ emb,
                    float*       __restrict__ out,     // concatenated tuple
                    int BS)                            // B*S = 256
{
    __shared__ SmemLayout sm;

    const int tid   = threadIdx.x;
    const int bs    = blockIdx.x / NCHUNK;
    const int chunk = blockIdx.x % NCHUNK;

    float* out_mean = out;                                      // [BS, D]
    float* out_sets = out + (size_t)BS * EMB_D;                 // 3 x [BS, A, D]
    const size_t set_stride = (size_t)BS * NARG * EMB_D;

    // ---- Phase 1: load ids / mask / arg ids; zero accumulators ----
    if (tid < L_TOK) {
        sm.s_ids[tid]  = sent_ids[(size_t)bs * L_TOK + tid];
        sm.s_m[tid]    = (float)att_mask[(size_t)bs * L_TOK + tid];
        sm.ev_cnt[tid] = 0;
    }
    if (tid < NP * NTOK) {                 // 192 threads
        int p = tid / NTOK, t = tid % NTOK;
        int set = p / NARG, a = p % NARG;
        const int* src = (set == 0) ? pred_ids : (set == 1) ? arg0_ids : arg1_ids;
        sm.s_arg[tid] = src[((size_t)bs * NARG + a) * NTOK + t];
    }
    if (tid < NP) sm.s_tot[tid] = 0;
    #pragma unroll
    for (int i = 0; i < NP; i++) sm.acc[i * BDIM + tid] = 0.f;
    __syncthreads();

    // ---- Phase 2: build per-TOKEN event lists (3072 tiny tasks) ----
    // Event for token l: (p, w) with w = #arg tokens of p matching sentence id l.
    for (int task = tid; task < NP * L_TOK; task += BDIM) {
        int p = task >> 7;          // /128
        int l = task & (L_TOK - 1);
        int sid = sm.s_ids[l];
        int w = 0;
        #pragma unroll
        for (int t = 0; t < NTOK; t++) {
            int aid = sm.s_arg[p * NTOK + t];
            w += (aid != 0 && aid == sid) ? 1 : 0;
        }
        if (w) {
            int pos = atomicAdd(&sm.ev_cnt[l], 1);
            sm.ev[l * NP + pos] = (unsigned short)(p | (w << 5));
            atomicAdd(&sm.s_tot[p], w);
        }
    }
    __syncthreads();

    if (tid == 0) {
        float ms = 0.f;
        #pragma unroll 8
        for (int l = 0; l < L_TOK; l++) ms += sm.s_m[l];
        sm.s_minv = 1.f / fmaxf(ms, 1.f);
    }
    if (tid < NP) {
        int tot = sm.s_tot[tid];
        sm.s_inv[tid] = (tot > 0) ? (1.f / (float)tot) : 0.f;  // 0 => where(counts>0,...,0)
    }
    __syncthreads();

    // ---- Phase 3: SINGLE streaming pass. Each value read from DRAM once. ----
    // Thread tid owns column (chunk*DC + tid); warp reads 128 contiguous
    // bytes per row -> fully coalesced, MLP=8.
    const float* col_base = emb + (size_t)bs * L_TOK * EMB_D
                                + (size_t)chunk * DC + tid;
    float* myacc = &sm.acc[tid];

    float a0 = 0.f, a1 = 0.f, a2 = 0.f, a3 = 0.f;
    float a4 = 0.f, a5 = 0.f, a6 = 0.f, a7 = 0.f;

    for (int l0 = 0; l0 < L_TOK; l0 += 8) {
        float v0 = col_base[(size_t)(l0 + 0) * EMB_D];
        float v1 = col_base[(size_t)(l0 + 1) * EMB_D];
        float v2 = col_base[(size_t)(l0 + 2) * EMB_D];
        float v3 = col_base[(size_t)(l0 + 3) * EMB_D];
        float v4 = col_base[(size_t)(l0 + 4) * EMB_D];
        float v5 = col_base[(size_t)(l0 + 5) * EMB_D];
        float v6 = col_base[(size_t)(l0 + 6) * EMB_D];
        float v7 = col_base[(size_t)(l0 + 7) * EMB_D];

        a0 += sm.s_m[l0 + 0] * v0;
        a1 += sm.s_m[l0 + 1] * v1;
        a2 += sm.s_m[l0 + 2] * v2;
        a3 += sm.s_m[l0 + 3] * v3;
        a4 += sm.s_m[l0 + 4] * v4;
        a5 += sm.s_m[l0 + 5] * v5;
        a6 += sm.s_m[l0 + 6] * v6;
        a7 += sm.s_m[l0 + 7] * v7;

        // Apply this batch's events into smem accumulators.
        // acc[p*BDIM+tid]: warp-uniform p => consecutive banks, conflict-free.
        float vv[8] = {v0, v1, v2, v3, v4, v5, v6, v7};
        #pragma unroll
        for (int k = 0; k < 8; k++) {
            const int l = l0 + k;
            const int cnt = sm.ev_cnt[l];              // uniform across block
            for (int j = 0; j < cnt; j++) {
                int e = sm.ev[l * NP + j];             // broadcast LDS
                int p = e & 31;
                float w = (float)(e >> 5);
                myacc[p * BDIM] += w * vv[k];
            }
        }
    }

    // ---- Epilogue ----
    float mean = (((a0 + a1) + (a2 + a3)) + ((a4 + a5) + (a6 + a7))) * sm.s_minv;
    out_mean[(size_t)bs * EMB_D + (size_t)chunk * DC + tid] = mean;

    // Each thread reads only its own accumulators -> no sync needed.
    #pragma unroll
    for (int p = 0; p < NP; p++) {
        float res = myacc[p * BDIM] * sm.s_inv[p];
        int set = p >> 3;
        int a   = p & 7;
        float* dst = out_sets + (size_t)set * set_stride;
        dst[((size_t)bs * NARG + a) * EMB_D + (size_t)chunk * DC + tid] = res;
    }
}

extern "C" void kernel_launch(void* const* d_in, const int* in_sizes, int n_in,
                              void* d_out, int out_size)
{
    const int*   sent = (const int*)  d_in[0];  // [B,S,L] int32
    const int*   mask = (const int*)  d_in[1];  // [B,S,L] int32
    const int*   pred = (const int*)  d_in[2];  // [B,S,A,T] int32
    const int*   a0   = (const int*)  d_in[3];
    const int*   a1   = (const int*)  d_in[4];
    const float* emb  = (const float*)d_in[5];  // [B,S,L,D] fp32
    float*       out  = (float*)      d_out;

    const int BS = in_sizes[0] / L_TOK;         // 256

    slmuse_fused_kernel<<<BS * NCHUNK, BDIM>>>(
        sent, mask, pred, a0, a1, emb, out, BS);
}